// round 2
// baseline (speedup 1.0000x reference)
#include <cuda_runtime.h>
#include <cstddef>

// Problem constants (from reference): B=1, L=2048, DIM=16, INNER=1.
// Math collapses: softmax over a size-1 axis == 1.0, so
//   out[i, j, d] = v[i] * W_out[d] + b_out[d],  v[i] = dot(x[i,:], W_qkv[2,:])
// Output is (1, 2048, 2048, 16) fp32 = 268 MB -> pure store-bandwidth problem.

#define L_TOKENS 2048
#define DIM_IN   16
#define ROW_F4   (L_TOKENS * DIM_IN / 4)   // 8192 float4 per i-row
#define THREADS  256

__global__ __launch_bounds__(THREADS, 8)
void attn_broadcast_kernel(const float* __restrict__ x,
                           const float* __restrict__ Wqkv,   // (3,16) row-major; v-row at +32
                           const float* __restrict__ Wout,   // (16,1)
                           const float* __restrict__ bout,   // (16,)
                           float4* __restrict__ out)
{
    const int i   = blockIdx.x;
    const int tid = threadIdx.x;

    __shared__ float4 pat[4];   // the 16-float output pattern for this i

    if (tid < 32) {
        // v[i] = dot(x[i, 0:16], Wqkv[2, 0:16])
        float prod = 0.0f;
        if (tid < 16)
            prod = x[i * DIM_IN + tid] * Wqkv[32 + tid];
        // reduce 16 lanes -> lane 0
        #pragma unroll
        for (int off = 8; off > 0; off >>= 1)
            prod += __shfl_down_sync(0xffffffffu, prod, off);
        float v = __shfl_sync(0xffffffffu, prod, 0);
        if (tid < 16)
            reinterpret_cast<float*>(pat)[tid] = v * Wout[tid] + bout[tid];
    }
    __syncthreads();

    // Stream the 16-float pattern across 2048 j positions.
    // THREADS % 4 == 0, so (k & 3) == (tid & 3) for every iteration:
    // each thread re-stores the same float4 register -> no shared reloads.
    const float4 val = pat[tid & 3];
    const size_t base = (size_t)i * ROW_F4;

    #pragma unroll 8
    for (int k = tid; k < ROW_F4; k += THREADS)
        __stcs(out + base + k, val);   // streaming store: no L2 reuse, evict-first
}

extern "C" void kernel_launch(void* const* d_in, const int* in_sizes, int n_in,
                              void* d_out, int out_size)
{
    const float* x    = (const float*)d_in[0];   // (1, 2048, 16)
    const float* Wqkv = (const float*)d_in[1];   // (3, 16)
    const float* Wout = (const float*)d_in[2];   // (16, 1)
    const float* bout = (const float*)d_in[3];   // (16,)
    float4* out = (float4*)d_out;                // (1, 2048, 2048, 16) fp32

    attn_broadcast_kernel<<<L_TOKENS, THREADS>>>(x, Wqkv, Wout, bout, out);
}